// round 8
// baseline (speedup 1.0000x reference)
#include <cuda_runtime.h>
#include <math.h>

// ContrastiveLoss, B=4096, D=1024, MARGIN=1.0, EPS=1e-8.
//
// MARGIN == 1.0 makes the off-diagonal hinge relu(cos_ij - 1) identically 0
// for unit vectors, so the loss reduces exactly to the diagonal terms. We read
// only the labels diagonal and stream the 3 feature matrices (48 MB).
//
// R8: evidence across R1-R7: streaming loop is at the achievable read roofline
// (~5.6TB/s wall-corrected; occ/MLP/cache-op/TMA all no-ops or regressions).
// Remaining cost is the serialized tail: final_reduce launch gap + reduce.
// Fix: PDL - final_reduce launched with programmatic stream serialization so
// its launch/prolog overlaps the streaming kernel's drain; it gates on
// cudaGridDependencySynchronize() before touching g_partial. Streaming kernel
// triggers completion right after publishing partials. Reduce vectorized.

#ifndef WARP_FULL_MASK
#define WARP_FULL_MASK 0xFFFFFFFFu
#endif

#define THREADS 256
#define NWARPS  (THREADS / 32)     // 8 warps -> 4 rows per block
#define ROWS_PER_BLOCK (NWARPS / 2)

static __device__ float g_partial[8192];   // per-row losses (B <= 8192)

__device__ __forceinline__ float warp_sum(float v) {
#pragma unroll
    for (int o = 16; o > 0; o >>= 1)
        v += __shfl_down_sync(WARP_FULL_MASK, v, o);
    return v;
}

// 2 warps per row (R5 structure, best measured): warp (2k+h) streams half h of
// row blockIdx.x*4+k. Half-row = D4/2 float4 -> 4 per lane per stream.
__global__ void __launch_bounds__(THREADS, 7)
row_loss_kernel(const float4* __restrict__ f0,
                const float4* __restrict__ f1,
                const float4* __restrict__ t,
                const float*  __restrict__ labels,
                int B, int D4)
{
    __shared__ float s_red[NWARPS][5];

    int tid  = threadIdx.x;
    int lane = tid & 31;
    int wid  = tid >> 5;
    int rloc = wid >> 1;           // 0..3 row within block
    int half = wid & 1;            // which half of the row
    int row  = blockIdx.x * ROWS_PER_BLOCK + rloc;

    float d0 = 0.f, d1 = 0.f, n0 = 0.f, n1 = 0.f, nt = 0.f;

    if (row < B) {
        int h4 = D4 >> 1;                                  // 128 for D=1024
        size_t base = (size_t)row * D4 + (size_t)half * h4;
        const float4* r0 = f0 + base;
        const float4* r1 = f1 + base;
        const float4* rt = t  + base;

        // 4 iterations/lane for D=1024; 3 LDG.128 per iter.
        for (int i = lane; i < h4; i += 32) {
            float4 a = __ldcs(r0 + i);
            float4 b = __ldcs(r1 + i);
            float4 c = __ldcs(rt + i);
            d0 += a.x * c.x + a.y * c.y + a.z * c.z + a.w * c.w;
            d1 += b.x * c.x + b.y * c.y + b.z * c.z + b.w * c.w;
            n0 += a.x * a.x + a.y * a.y + a.z * a.z + a.w * a.w;
            n1 += b.x * b.x + b.y * b.y + b.z * b.z + b.w * b.w;
            nt += c.x * c.x + c.y * c.y + c.z * c.z + c.w * c.w;
        }
    }

    d0 = warp_sum(d0);
    d1 = warp_sum(d1);
    n0 = warp_sum(n0);
    n1 = warp_sum(n1);
    nt = warp_sum(nt);

    if (lane == 0) {
        s_red[wid][0] = d0;
        s_red[wid][1] = d1;
        s_red[wid][2] = n0;
        s_red[wid][3] = n1;
        s_red[wid][4] = nt;
    }
    __syncthreads();

    // 4 threads finish 4 rows: combine the two half-row partials.
    if (tid < ROWS_PER_BLOCK) {
        int r = blockIdx.x * ROWS_PER_BLOCK + tid;
        if (r < B) {
            float v0 = s_red[2 * tid][0] + s_red[2 * tid + 1][0];
            float v1 = s_red[2 * tid][1] + s_red[2 * tid + 1][1];
            float v2 = s_red[2 * tid][2] + s_red[2 * tid + 1][2];
            float v3 = s_red[2 * tid][3] + s_red[2 * tid + 1][3];
            float v4 = s_red[2 * tid][4] + s_red[2 * tid + 1][4];

            const float EPS = 1e-8f;
            float inv_t = 1.0f / fmaxf(sqrtf(v4), EPS);
            float cos0  = v0 * (1.0f / fmaxf(sqrtf(v2), EPS)) * inv_t;
            float cos1  = v1 * (1.0f / fmaxf(sqrtf(v3), EPS)) * inv_t;
            float L     = labels[(size_t)r * B + r];   // diagonal label
            g_partial[r] =
                  L * (1.0f - cos0) + (1.0f - L) * fmaxf(cos0 - 1.0f, 0.0f)
                + L * (1.0f - cos1) + (1.0f - L) * fmaxf(cos1 - 1.0f, 0.0f);
        }
    }

    // PDL: partials for this block are published; allow the dependent
    // final_reduce kernel to begin launching.
    cudaTriggerProgrammaticLaunchCompletion();
}

// Deterministic single-block reduction of the B per-row partials.
// Launched with programmatic stream serialization: prolog overlaps the
// streaming kernel; the grid-dependency sync gates the g_partial reads.
__global__ void __launch_bounds__(THREADS)
final_reduce_kernel(float* __restrict__ out, int B)
{
    __shared__ float sdata[NWARPS];
    int tid = threadIdx.x;

    cudaGridDependencySynchronize();   // wait for row_loss_kernel completion

    const float4* p4 = (const float4*)g_partial;
    int n4 = B >> 2;                   // 1024 for B=4096
    float s = 0.f;
    for (int i = tid; i < n4; i += THREADS) {
        float4 v = p4[i];
        s += v.x + v.y + v.z + v.w;
    }
    for (int i = (n4 << 2) + tid; i < B; i += THREADS)   // remainder
        s += g_partial[i];

    s = warp_sum(s);
    if ((tid & 31) == 0) sdata[tid >> 5] = s;
    __syncthreads();

    if (tid < 32) {
        float v = (tid < NWARPS) ? sdata[tid] : 0.f;
#pragma unroll
        for (int o = NWARPS / 2; o > 0; o >>= 1)
            v += __shfl_down_sync(WARP_FULL_MASK, v, o);
        if (tid == 0)
            out[0] = v / ((float)B * (float)B);
    }
}

extern "C" void kernel_launch(void* const* d_in, const int* in_sizes, int n_in,
                              void* d_out, int out_size)
{
    const float* f0     = (const float*)d_in[0];
    const float* f1     = (const float*)d_in[1];
    const float* t      = (const float*)d_in[2];
    const float* labels = (const float*)d_in[3];

    long long nl = in_sizes[3];
    int B = (int)(sqrt((double)nl) + 0.5);
    int D = in_sizes[0] / B;
    int D4 = D / 4;

    int blocks = (B + ROWS_PER_BLOCK - 1) / ROWS_PER_BLOCK;  // 1024 for B=4096

    row_loss_kernel<<<blocks, THREADS>>>(
        (const float4*)f0, (const float4*)f1, (const float4*)t,
        labels, B, D4);

    // Launch the reduce with PDL so its launch latency overlaps the
    // streaming kernel's drain.
    {
        cudaLaunchConfig_t cfg = {};
        cfg.gridDim  = dim3(1, 1, 1);
        cfg.blockDim = dim3(THREADS, 1, 1);
        cfg.dynamicSmemBytes = 0;
        cfg.stream = 0;
        cudaLaunchAttribute attr[1];
        attr[0].id = cudaLaunchAttributeProgrammaticStreamSerialization;
        attr[0].val.programmaticStreamSerializationAllowed = 1;
        cfg.attrs = attr;
        cfg.numAttrs = 1;
        float* out = (float*)d_out;
        cudaError_t e = cudaLaunchKernelEx(&cfg, final_reduce_kernel, out, B);
        if (e != cudaSuccess) {
            // Fallback: plain launch (still correct, just serialized).
            final_reduce_kernel<<<1, THREADS>>>(out, B);
        }
    }
}

// round 9
// speedup vs baseline: 2.4438x; 2.4438x over previous
#include <cuda_runtime.h>
#include <math.h>

// ContrastiveLoss, B=4096, D=1024, MARGIN=1.0, EPS=1e-8.
//
// MARGIN == 1.0 makes the off-diagonal hinge relu(cos_ij - 1) identically 0
// for unit vectors, so the loss reduces exactly to the diagonal terms. We read
// only the labels diagonal and stream the 3 feature matrices (48 MB).
//
// R9: consolidation. Eight rounds establish the streaming loop at the machine
// floor (~10.75us total; invariant to occ 43-87%, cache-op, access order;
// MLP>3, TMA bulk, and PDL all regress). Keep the R5 streaming structure
// verbatim; shave the only remaining addressable cost (reduce tail):
//  - streaming kernel emits ONE partial per block (1024 instead of 4096)
//  - reduce kernel: 256 thr x 1 float4, single warp-level combine.

#ifndef WARP_FULL_MASK
#define WARP_FULL_MASK 0xFFFFFFFFu
#endif

#define THREADS 256
#define NWARPS  (THREADS / 32)     // 8 warps -> 4 rows per block
#define ROWS_PER_BLOCK (NWARPS / 2)

static __device__ float g_partial[4096];   // per-BLOCK partial sums

__device__ __forceinline__ float warp_sum(float v) {
#pragma unroll
    for (int o = 16; o > 0; o >>= 1)
        v += __shfl_down_sync(WARP_FULL_MASK, v, o);
    return v;
}

// 2 warps per row (R5 structure, best measured): warp (2k+h) streams half h of
// row blockIdx.x*4+k. Half-row = D4/2 float4 -> 4 per lane per stream.
__global__ void __launch_bounds__(THREADS, 7)
row_loss_kernel(const float4* __restrict__ f0,
                const float4* __restrict__ f1,
                const float4* __restrict__ t,
                const float*  __restrict__ labels,
                int B, int D4)
{
    __shared__ float s_red[NWARPS][5];
    __shared__ float s_loss[ROWS_PER_BLOCK];

    int tid  = threadIdx.x;
    int lane = tid & 31;
    int wid  = tid >> 5;
    int rloc = wid >> 1;           // 0..3 row within block
    int half = wid & 1;            // which half of the row
    int row  = blockIdx.x * ROWS_PER_BLOCK + rloc;

    float d0 = 0.f, d1 = 0.f, n0 = 0.f, n1 = 0.f, nt = 0.f;

    if (row < B) {
        int h4 = D4 >> 1;                                  // 128 for D=1024
        size_t base = (size_t)row * D4 + (size_t)half * h4;
        const float4* r0 = f0 + base;
        const float4* r1 = f1 + base;
        const float4* rt = t  + base;

        // 4 iterations/lane for D=1024; 3 LDG.128 per iter.
        for (int i = lane; i < h4; i += 32) {
            float4 a = __ldcs(r0 + i);
            float4 b = __ldcs(r1 + i);
            float4 c = __ldcs(rt + i);
            d0 += a.x * c.x + a.y * c.y + a.z * c.z + a.w * c.w;
            d1 += b.x * c.x + b.y * c.y + b.z * c.z + b.w * c.w;
            n0 += a.x * a.x + a.y * a.y + a.z * a.z + a.w * a.w;
            n1 += b.x * b.x + b.y * b.y + b.z * b.z + b.w * b.w;
            nt += c.x * c.x + c.y * c.y + c.z * c.z + c.w * c.w;
        }
    }

    d0 = warp_sum(d0);
    d1 = warp_sum(d1);
    n0 = warp_sum(n0);
    n1 = warp_sum(n1);
    nt = warp_sum(nt);

    if (lane == 0) {
        s_red[wid][0] = d0;
        s_red[wid][1] = d1;
        s_red[wid][2] = n0;
        s_red[wid][3] = n1;
        s_red[wid][4] = nt;
    }
    __syncthreads();

    // 4 threads finish 4 rows: combine the two half-row partials.
    if (tid < ROWS_PER_BLOCK) {
        float loss = 0.f;
        int r = blockIdx.x * ROWS_PER_BLOCK + tid;
        if (r < B) {
            float v0 = s_red[2 * tid][0] + s_red[2 * tid + 1][0];
            float v1 = s_red[2 * tid][1] + s_red[2 * tid + 1][1];
            float v2 = s_red[2 * tid][2] + s_red[2 * tid + 1][2];
            float v3 = s_red[2 * tid][3] + s_red[2 * tid + 1][3];
            float v4 = s_red[2 * tid][4] + s_red[2 * tid + 1][4];

            const float EPS = 1e-8f;
            float inv_t = 1.0f / fmaxf(sqrtf(v4), EPS);
            float cos0  = v0 * (1.0f / fmaxf(sqrtf(v2), EPS)) * inv_t;
            float cos1  = v1 * (1.0f / fmaxf(sqrtf(v3), EPS)) * inv_t;
            float L     = labels[(size_t)r * B + r];   // diagonal label
            loss = L * (1.0f - cos0) + (1.0f - L) * fmaxf(cos0 - 1.0f, 0.0f)
                 + L * (1.0f - cos1) + (1.0f - L) * fmaxf(cos1 - 1.0f, 0.0f);
        }
        s_loss[tid] = loss;
    }
    __syncthreads();

    // One partial per block.
    if (tid == 0) {
        float s = 0.f;
#pragma unroll
        for (int k = 0; k < ROWS_PER_BLOCK; k++) s += s_loss[k];
        g_partial[blockIdx.x] = s;
    }
}

// Deterministic reduction of the per-block partials (nblocks <= 4096).
__global__ void __launch_bounds__(THREADS)
final_reduce_kernel(float* __restrict__ out, int nblocks, float inv_b2)
{
    __shared__ float sdata[NWARPS];
    int tid = threadIdx.x;

    const float4* p4 = (const float4*)g_partial;
    int n4 = nblocks >> 2;                 // 256 for 1024 blocks
    float s = 0.f;
    for (int i = tid; i < n4; i += THREADS) {
        float4 v = p4[i];
        s += v.x + v.y + v.z + v.w;
    }
    for (int i = (n4 << 2) + tid; i < nblocks; i += THREADS)  // remainder
        s += g_partial[i];

    s = warp_sum(s);
    if ((tid & 31) == 0) sdata[tid >> 5] = s;
    __syncthreads();

    if (tid < 32) {
        float v = (tid < NWARPS) ? sdata[tid] : 0.f;
#pragma unroll
        for (int o = NWARPS / 2; o > 0; o >>= 1)
            v += __shfl_down_sync(WARP_FULL_MASK, v, o);
        if (tid == 0)
            out[0] = v * inv_b2;
    }
}

extern "C" void kernel_launch(void* const* d_in, const int* in_sizes, int n_in,
                              void* d_out, int out_size)
{
    const float* f0     = (const float*)d_in[0];
    const float* f1     = (const float*)d_in[1];
    const float* t      = (const float*)d_in[2];
    const float* labels = (const float*)d_in[3];

    long long nl = in_sizes[3];
    int B = (int)(sqrt((double)nl) + 0.5);
    int D = in_sizes[0] / B;
    int D4 = D / 4;

    int blocks = (B + ROWS_PER_BLOCK - 1) / ROWS_PER_BLOCK;  // 1024 for B=4096

    row_loss_kernel<<<blocks, THREADS>>>(
        (const float4*)f0, (const float4*)f1, (const float4*)t,
        labels, B, D4);

    float inv_b2 = 1.0f / ((float)B * (float)B);
    final_reduce_kernel<<<1, THREADS>>>((float*)d_out, blocks, inv_b2);
}